// round 14
// baseline (speedup 1.0000x reference)
#include <cuda_runtime.h>
#include <cstddef>
#include <cstdint>

// Problem constants
#define Bv 64
#define Nv 2048
#define Ev 16384
#define Fv 32
#define Hv 64
#define Kv 8
#define Cv 16
#define Gv 64
#define CKv 128          // C*K
#define NGv 131072       // N*G
#define CAPE 64          // max nodes per edge (mean 8)
#define CAPN 192         // max edges per node (mean 64)
#define CAPNP (CAPN + 8) // padded edge list (prefetch overrun guard)
#define GRID4 592        // persistent K4 grid = 4 CTAs x 148 SMs

// fused front kernel block ranges
#define NB_LINC 256      // linc scan: 256 blocks x 8 warps = 2048 node rows
#define NB_K0   64       // edge MLP: 64 blocks x 256 threads = 16384 edges
#define NB_EDGE 2048     // rinc scan + gather: 2048 blocks x 8 warps = 16384 edges

typedef unsigned long long u64;

__device__ __forceinline__ u64 pack2(float lo, float hi) {
    u64 r; asm("mov.b64 %0,{%1,%2};" : "=l"(r) : "f"(lo), "f"(hi)); return r;
}
__device__ __forceinline__ void ffma2(u64& d, u64 a, u64 b) {
    asm("fma.rn.f32x2 %0,%1,%2,%0;" : "+l"(d) : "l"(a), "l"(b));
}
__device__ __forceinline__ void unpack2(float& lo, float& hi, u64 v) {
    asm("mov.b64 {%0,%1},%2;" : "=f"(lo), "=f"(hi) : "l"(v));
}
__device__ __forceinline__ float hsum2(u64 v) {
    float lo, hi; unpack2(lo, hi, v);
    return lo + hi;
}

// ---------------- scratch (device globals; no allocation) ----------------
__device__ float g_w[Ev * Kv];                 // per-edge kernel weights [E,K]
__device__ int   g_ncnt[Nv];
__device__ int   g_nedges[Nv * CAPN];          // linc CSR: edges per node
__device__ float g_z[(size_t)Ev * Bv * Cv];    // z in (E,B,C) layout, 67MB

// ---------------- ordered sparse row scan (deterministic compaction) ---------
template <int COLS, int CAP, int UNROLL>
__device__ __forceinline__ int scan_row(const float* __restrict__ row,
                                        int* __restrict__ outp, int lane) {
    int cnt = 0;
    const float4* r4 = (const float4*)row;
    const unsigned lt = (1u << lane) - 1u;
    for (int g = 0; g < COLS / 128; g += UNROLL) {
        float4 v[UNROLL];
#pragma unroll
        for (int u = 0; u < UNROLL; ++u) v[u] = r4[(size_t)(g + u) * 32 + lane];
#pragma unroll
        for (int u = 0; u < UNROLL; ++u) {
            float a0 = v[u].x, a1 = v[u].y, a2 = v[u].z, a3 = v[u].w;
            unsigned m0 = __ballot_sync(0xffffffffu, a0 != 0.0f);
            unsigned m1 = __ballot_sync(0xffffffffu, a1 != 0.0f);
            unsigned m2 = __ballot_sync(0xffffffffu, a2 != 0.0f);
            unsigned m3 = __ballot_sync(0xffffffffu, a3 != 0.0f);
            int prefix = __popc(m0 & lt) + __popc(m1 & lt) + __popc(m2 & lt) + __popc(m3 & lt);
            int base = (g + u) * 128 + lane * 4;
            int own = 0;
            if (a0 != 0.0f) { int p = cnt + prefix + own; if (p < CAP) outp[p] = base + 0; own++; }
            if (a1 != 0.0f) { int p = cnt + prefix + own; if (p < CAP) outp[p] = base + 1; own++; }
            if (a2 != 0.0f) { int p = cnt + prefix + own; if (p < CAP) outp[p] = base + 2; own++; }
            if (a3 != 0.0f) { int p = cnt + prefix + own; if (p < CAP) outp[p] = base + 3; own++; }
            cnt += __popc(m0) + __popc(m1) + __popc(m2) + __popc(m3);
        }
    }
    return (cnt < CAP) ? cnt : CAP;
}

// ---------------- K123: fused linc scan | edge MLP | rinc scan + gather ------
__global__ void k123(const float* __restrict__ rinc,
                     const float* __restrict__ linc,
                     const float* __restrict__ x,
                     const float* __restrict__ ef,
                     const float* __restrict__ w1, const float* __restrict__ b1,
                     const float* __restrict__ w2, const float* __restrict__ b2) {
    __shared__ int   nbuf[8][CAPE];    // per-warp node lists (gather branch)
    __shared__ float w1s[Hv * Fv];     // k0 branch
    __shared__ float w2s[Kv * Hv];
    __shared__ float b1s[Hv];
    __shared__ float b2s[Kv];

    int bid = blockIdx.x;
    int t = threadIdx.x;
    int wid = t >> 5, lane = t & 31;

    if (bid < NB_LINC) {
        int n = bid * 8 + wid;
        int c = scan_row<Ev, CAPN, 8>(linc + (size_t)n * Ev,
                                      g_nedges + (size_t)n * CAPN, lane);
        if (lane == 0) g_ncnt[n] = c;
    } else if (bid < NB_LINC + NB_K0) {
        int e = (bid - NB_LINC) * 256 + t;
        for (int i = t; i < Hv * Fv; i += 256) w1s[i] = w1[i];
        for (int i = t; i < Kv * Hv; i += 256) w2s[i] = w2[i];
        if (t < Hv) b1s[t] = b1[t];
        if (t < Kv) b2s[t] = b2[t];
        __syncthreads();

        float efr[Fv];
#pragma unroll
        for (int q = 0; q < Fv / 4; ++q)
            ((float4*)efr)[q] = ((const float4*)(ef + (size_t)e * Fv))[q];
        float wk[Kv];
#pragma unroll
        for (int k = 0; k < Kv; ++k) wk[k] = b2s[k];
        for (int j = 0; j < Hv; ++j) {
            float s = b1s[j];
#pragma unroll
            for (int f = 0; f < Fv; ++f) s += efr[f] * w1s[j * Fv + f];
            s = fmaxf(s, 0.0f);
#pragma unroll
            for (int k = 0; k < Kv; ++k) wk[k] += s * w2s[k * Hv + j];
        }
#pragma unroll
        for (int k = 0; k < Kv; ++k) g_w[e * Kv + k] = wk[k];
    } else {
        int e = (bid - NB_LINC - NB_K0) * 8 + wid;
        int cnt = scan_row<Nv, CAPE, 4>(rinc + (size_t)e * Nv, nbuf[wid], lane);
        __syncwarp();
        int myn0 = (lane < cnt) ? nbuf[wid][lane] : 0;
        int myn1 = (32 + lane < cnt) ? nbuf[wid][32 + lane] : 0;

        const int boff = (lane >> 2) * (Nv * Cv / 4) + (lane & 3);

        float4 acc[8];
#pragma unroll
        for (int q = 0; q < 8; ++q) acc[q] = make_float4(0.f, 0.f, 0.f, 0.f);

        const float4* x4 = (const float4*)x;
        for (int i = 0; i < cnt; ++i) {
            int nn = (i < 32) ? __shfl_sync(0xffffffffu, myn0, i)
                              : __shfl_sync(0xffffffffu, myn1, i - 32);
            const float4* xn = x4 + (size_t)nn * (Cv / 4) + boff;
#pragma unroll
            for (int q = 0; q < 8; ++q) {
                float4 v = xn[(size_t)q * 8 * (Nv * Cv / 4)];
                acc[q].x += v.x; acc[q].y += v.y; acc[q].z += v.z; acc[q].w += v.w;
            }
        }

        float4* zw = (float4*)(g_z + (size_t)e * (Bv * Cv));
#pragma unroll
        for (int q = 0; q < 8; ++q) zw[q * 32 + lane] = acc[q];
    }
}

// ---------------- K4: persistent fused per-node y + GEMM + relu --------------
// grid 592 (4 CTAs/SM): smem 32768 B only (y_s; wdup/el_s overlaid inside).
// gcw read via warp-uniform __ldg (32KB, stays hot in per-SM L1 across the
// node loop). __launch_bounds__(256,4) caps regs at 64 -> 32 warps/SM.
#define SMEM4 32768
__global__ void __launch_bounds__(256, 4) k4_main(const float* __restrict__ gcw,
                                                  const float* __restrict__ gcb,
                                                  float* __restrict__ out) {
    extern __shared__ char smem[];
    u64*   y_s   = (u64*)smem;                     // 32KB (transposed+swizzled)
    u64*   wdup  = (u64*)smem;                     // overlay: k-duplicated w (12288B)
    int*   el_s  = (int*)(smem + 12288);           // overlay: padded edge list (800B)

    int t = threadIdx.x;

    const int bq = t & 31, gq = t >> 5;            // stage-2 mapping
    const float4 cb0 = __ldg((const float4*)gcb + gq * 2);
    const float4 cb1 = __ldg((const float4*)gcb + gq * 2 + 1);
    const int b = t >> 2, cq = t & 3;              // stage-1 mapping
    const size_t zoff = (size_t)b * Cv + cq * 4;
    const int bx = b ^ (cq << 2);                  // swizzled y column (write side)
    const ulonglong2* gc2 = (const ulonglong2*)gcw;  // [g*32 + j2/2] pairs

    for (int n = blockIdx.x; n < Nv; n += GRID4) {
        __syncthreads();                           // y_s consumed; safe to overlay

        int cnt = g_ncnt[n];
        if (t < CAPNP) el_s[t] = (t < cnt) ? g_nedges[(size_t)n * CAPN + t] : 0;
        if (t < CAPN) {
            if (t < cnt) {
                int e = el_s[t];
                float4 wa = *(const float4*)(g_w + (size_t)e * 8);
                float4 wb = *(const float4*)(g_w + (size_t)e * 8 + 4);
                wdup[t * 8 + 0] = pack2(wa.x, wa.x); wdup[t * 8 + 1] = pack2(wa.y, wa.y);
                wdup[t * 8 + 2] = pack2(wa.z, wa.z); wdup[t * 8 + 3] = pack2(wa.w, wa.w);
                wdup[t * 8 + 4] = pack2(wb.x, wb.x); wdup[t * 8 + 5] = pack2(wb.y, wb.y);
                wdup[t * 8 + 6] = pack2(wb.z, wb.z); wdup[t * 8 + 7] = pack2(wb.w, wb.w);
            } else {
#pragma unroll
                for (int k = 0; k < 8; ++k) wdup[t * 8 + k] = 0ull;
            }
        }
        __syncthreads();

        // ---- stage 1: acc2[cp][k] += zpair(cp) * wdup(k); depth-2 prefetch ----
        u64 acc2[2][8];
#pragma unroll
        for (int cp = 0; cp < 2; ++cp)
#pragma unroll
            for (int k = 0; k < 8; ++k) acc2[cp][k] = 0ull;

        const ulonglong2* w_s2 = (const ulonglong2*)wdup;
        int cnt2 = (cnt + 1) & ~1;                 // padded iters are exact zeros

        float4 pz[2];
#pragma unroll
        for (int u = 0; u < 2; ++u)
            pz[u] = *(const float4*)(g_z + (size_t)el_s[u] * (Bv * Cv) + zoff);

        for (int i = 0; i < cnt2; i += 2) {
#pragma unroll
            for (int u = 0; u < 2; ++u) {
                float4 zv = pz[u];
                pz[u] = *(const float4*)(g_z + (size_t)el_s[i + 2 + u] * (Bv * Cv) + zoff);
                u64 zp0 = pack2(zv.x, zv.y);
                u64 zp1 = pack2(zv.z, zv.w);
                ulonglong2 wd0 = w_s2[(i + u) * 4 + 0];
                ulonglong2 wd1 = w_s2[(i + u) * 4 + 1];
                ulonglong2 wd2 = w_s2[(i + u) * 4 + 2];
                ulonglong2 wd3 = w_s2[(i + u) * 4 + 3];
                ffma2(acc2[0][0], zp0, wd0.x); ffma2(acc2[0][1], zp0, wd0.y);
                ffma2(acc2[0][2], zp0, wd1.x); ffma2(acc2[0][3], zp0, wd1.y);
                ffma2(acc2[0][4], zp0, wd2.x); ffma2(acc2[0][5], zp0, wd2.y);
                ffma2(acc2[0][6], zp0, wd3.x); ffma2(acc2[0][7], zp0, wd3.y);
                ffma2(acc2[1][0], zp1, wd0.x); ffma2(acc2[1][1], zp1, wd0.y);
                ffma2(acc2[1][2], zp1, wd1.x); ffma2(acc2[1][3], zp1, wd1.y);
                ffma2(acc2[1][4], zp1, wd2.x); ffma2(acc2[1][5], zp1, wd2.y);
                ffma2(acc2[1][6], zp1, wd3.x); ffma2(acc2[1][7], zp1, wd3.y);
            }
        }

        // repack c-pairs -> k-pairs (bit-exact)
        float alo[2][8], ahi[2][8];
#pragma unroll
        for (int cp = 0; cp < 2; ++cp)
#pragma unroll
            for (int k = 0; k < 8; ++k) unpack2(alo[cp][k], ahi[cp][k], acc2[cp][k]);

        __syncthreads();                           // wdup/el_s dead

        // write y: slot(j,b) = j*64 + bx  (bx = b ^ 4*cq; j>>4 == cq here)
#pragma unroll
        for (int ci = 0; ci < 4; ++ci) {
            int cp = ci >> 1, eo = ci & 1;
#pragma unroll
            for (int kq = 0; kq < 4; ++kq) {
                float v0 = eo ? ahi[cp][2 * kq]     : alo[cp][2 * kq];
                float v1 = eo ? ahi[cp][2 * kq + 1] : alo[cp][2 * kq + 1];
                int j = (cq * 4 + ci) * 4 + kq;
                y_s[j * 64 + bx] = pack2(v0, v1);
            }
        }
        __syncthreads();

        // ---- stage 2: out[b][g] = relu(sum_j y[j][b]*gcw[g][j] + gcb[g]) ----
        // b in {bq, bq+32}; g in gq*8..gq*8+7; g loads warp-uniform __ldg (L1-hot)
        u64 a2[2][8];
#pragma unroll
        for (int ib = 0; ib < 2; ++ib)
#pragma unroll
            for (int ig = 0; ig < 8; ++ig) a2[ib][ig] = 0ull;

#pragma unroll 2
        for (int j2 = 0; j2 < 64; j2 += 2) {
            int c4 = (j2 >> 4) << 2;
            u64 ya0 = y_s[j2 * 64 + (bq ^ c4)];
            u64 ya1 = y_s[j2 * 64 + ((bq + 32) ^ c4)];
            u64 yb0 = y_s[(j2 + 1) * 64 + (bq ^ c4)];
            u64 yb1 = y_s[(j2 + 1) * 64 + ((bq + 32) ^ c4)];
#pragma unroll
            for (int h = 0; h < 2; ++h) {
                ulonglong2 gv[4];
#pragma unroll
                for (int m = 0; m < 4; ++m)
                    gv[m] = __ldg(gc2 + (gq * 8 + h * 4 + m) * 32 + (j2 >> 1));
#pragma unroll
                for (int m = 0; m < 4; ++m) {      // j = j2 first (order preserved)
                    ffma2(a2[0][h * 4 + m], ya0, gv[m].x);
                    ffma2(a2[1][h * 4 + m], ya1, gv[m].x);
                }
#pragma unroll
                for (int m = 0; m < 4; ++m) {      // then j = j2+1
                    ffma2(a2[0][h * 4 + m], yb0, gv[m].y);
                    ffma2(a2[1][h * 4 + m], yb1, gv[m].y);
                }
            }
        }

#pragma unroll
        for (int ib = 0; ib < 2; ++ib) {
            int bb = bq + 32 * ib;
            float4 o0, o1;
            o0.x = fmaxf(hsum2(a2[ib][0]) + cb0.x, 0.0f);
            o0.y = fmaxf(hsum2(a2[ib][1]) + cb0.y, 0.0f);
            o0.z = fmaxf(hsum2(a2[ib][2]) + cb0.z, 0.0f);
            o0.w = fmaxf(hsum2(a2[ib][3]) + cb0.w, 0.0f);
            o1.x = fmaxf(hsum2(a2[ib][4]) + cb1.x, 0.0f);
            o1.y = fmaxf(hsum2(a2[ib][5]) + cb1.y, 0.0f);
            o1.z = fmaxf(hsum2(a2[ib][6]) + cb1.z, 0.0f);
            o1.w = fmaxf(hsum2(a2[ib][7]) + cb1.w, 0.0f);
            float* op = out + (size_t)bb * NGv + n * Gv + gq * 8;
            *(float4*)op = o0;
            *(float4*)(op + 4) = o1;
        }
    }
}

// ---------------- launcher ----------------
extern "C" void kernel_launch(void* const* d_in, const int* in_sizes, int n_in,
                              void* d_out, int out_size) {
    const float* x    = (const float*)d_in[0];
    const float* linc = (const float*)d_in[1];
    const float* rinc = (const float*)d_in[2];
    const float* ef   = (const float*)d_in[3];
    const float* w1   = (const float*)d_in[4];
    const float* b1   = (const float*)d_in[5];
    const float* w2   = (const float*)d_in[6];
    const float* b2   = (const float*)d_in[7];
    const float* gcw  = (const float*)d_in[8];
    const float* gcb  = (const float*)d_in[9];
    float* out = (float*)d_out;

    (void)in_sizes; (void)n_in; (void)out_size;

    cudaFuncSetAttribute(k4_main, cudaFuncAttributeMaxDynamicSharedMemorySize, SMEM4);

    k123<<<NB_LINC + NB_K0 + NB_EDGE, 256>>>(rinc, linc, x, ef, w1, b1, w2, b2);
    k4_main<<<GRID4, 256, SMEM4>>>(gcw, gcb, out);
}

// round 15
// speedup vs baseline: 1.1896x; 1.1896x over previous
#include <cuda_runtime.h>
#include <cstddef>
#include <cstdint>

// Problem constants
#define Bv 64
#define Nv 2048
#define Ev 16384
#define Fv 32
#define Hv 64
#define Kv 8
#define Cv 16
#define Gv 64
#define CKv 128          // C*K
#define NGv 131072       // N*G
#define CAPE 64          // max nodes per edge (mean 8)
#define CAPN 192         // max edges per node (mean 64)
#define CAPNP (CAPN + 8) // padded edge list (prefetch overrun guard)
#define GRID4 444        // persistent K4 grid = 3 CTAs x 148 SMs

// fused front kernel block ranges
#define NB_LINC 256      // linc scan: 256 blocks x 8 warps = 2048 node rows
#define NB_K0   64       // edge MLP: 64 blocks x 256 threads = 16384 edges
#define NB_EDGE 2048     // rinc scan + gather: 2048 blocks x 8 warps = 16384 edges

typedef unsigned long long u64;

__device__ __forceinline__ u64 pack2(float lo, float hi) {
    u64 r; asm("mov.b64 %0,{%1,%2};" : "=l"(r) : "f"(lo), "f"(hi)); return r;
}
__device__ __forceinline__ void ffma2(u64& d, u64 a, u64 b) {
    asm("fma.rn.f32x2 %0,%1,%2,%0;" : "+l"(d) : "l"(a), "l"(b));
}
__device__ __forceinline__ void unpack2(float& lo, float& hi, u64 v) {
    asm("mov.b64 {%0,%1},%2;" : "=f"(lo), "=f"(hi) : "l"(v));
}
__device__ __forceinline__ float hsum2(u64 v) {
    float lo, hi; unpack2(lo, hi, v);
    return lo + hi;
}

// ---------------- scratch (device globals; no allocation) ----------------
__device__ float g_w[Ev * Kv];                 // per-edge kernel weights [E,K]
__device__ int   g_ncnt[Nv];
__device__ int   g_nedges[Nv * CAPN];          // linc CSR: edges per node
__device__ float g_z[(size_t)Ev * Bv * Cv];    // z in (E,B,C) layout, 67MB

// ---------------- ordered sparse row scan (deterministic compaction) ---------
template <int COLS, int CAP, int UNROLL>
__device__ __forceinline__ int scan_row(const float* __restrict__ row,
                                        int* __restrict__ outp, int lane) {
    int cnt = 0;
    const float4* r4 = (const float4*)row;
    const unsigned lt = (1u << lane) - 1u;
    for (int g = 0; g < COLS / 128; g += UNROLL) {
        float4 v[UNROLL];
#pragma unroll
        for (int u = 0; u < UNROLL; ++u) v[u] = r4[(size_t)(g + u) * 32 + lane];
#pragma unroll
        for (int u = 0; u < UNROLL; ++u) {
            float a0 = v[u].x, a1 = v[u].y, a2 = v[u].z, a3 = v[u].w;
            unsigned m0 = __ballot_sync(0xffffffffu, a0 != 0.0f);
            unsigned m1 = __ballot_sync(0xffffffffu, a1 != 0.0f);
            unsigned m2 = __ballot_sync(0xffffffffu, a2 != 0.0f);
            unsigned m3 = __ballot_sync(0xffffffffu, a3 != 0.0f);
            int prefix = __popc(m0 & lt) + __popc(m1 & lt) + __popc(m2 & lt) + __popc(m3 & lt);
            int base = (g + u) * 128 + lane * 4;
            int own = 0;
            if (a0 != 0.0f) { int p = cnt + prefix + own; if (p < CAP) outp[p] = base + 0; own++; }
            if (a1 != 0.0f) { int p = cnt + prefix + own; if (p < CAP) outp[p] = base + 1; own++; }
            if (a2 != 0.0f) { int p = cnt + prefix + own; if (p < CAP) outp[p] = base + 2; own++; }
            if (a3 != 0.0f) { int p = cnt + prefix + own; if (p < CAP) outp[p] = base + 3; own++; }
            cnt += __popc(m0) + __popc(m1) + __popc(m2) + __popc(m3);
        }
    }
    return (cnt < CAP) ? cnt : CAP;
}

// ---------------- K123: fused linc scan | edge MLP | rinc scan + gather ------
__global__ void k123(const float* __restrict__ rinc,
                     const float* __restrict__ linc,
                     const float* __restrict__ x,
                     const float* __restrict__ ef,
                     const float* __restrict__ w1, const float* __restrict__ b1,
                     const float* __restrict__ w2, const float* __restrict__ b2) {
    __shared__ int   nbuf[8][CAPE];    // per-warp node lists (gather branch)
    __shared__ float w1s[Hv * Fv];     // k0 branch
    __shared__ float w2s[Kv * Hv];
    __shared__ float b1s[Hv];
    __shared__ float b2s[Kv];

    int bid = blockIdx.x;
    int t = threadIdx.x;
    int wid = t >> 5, lane = t & 31;

    if (bid < NB_LINC) {
        int n = bid * 8 + wid;
        int c = scan_row<Ev, CAPN, 8>(linc + (size_t)n * Ev,
                                      g_nedges + (size_t)n * CAPN, lane);
        if (lane == 0) g_ncnt[n] = c;
    } else if (bid < NB_LINC + NB_K0) {
        int e = (bid - NB_LINC) * 256 + t;
        for (int i = t; i < Hv * Fv; i += 256) w1s[i] = w1[i];
        for (int i = t; i < Kv * Hv; i += 256) w2s[i] = w2[i];
        if (t < Hv) b1s[t] = b1[t];
        if (t < Kv) b2s[t] = b2[t];
        __syncthreads();

        float efr[Fv];
#pragma unroll
        for (int q = 0; q < Fv / 4; ++q)
            ((float4*)efr)[q] = ((const float4*)(ef + (size_t)e * Fv))[q];
        float wk[Kv];
#pragma unroll
        for (int k = 0; k < Kv; ++k) wk[k] = b2s[k];
        for (int j = 0; j < Hv; ++j) {
            float s = b1s[j];
#pragma unroll
            for (int f = 0; f < Fv; ++f) s += efr[f] * w1s[j * Fv + f];
            s = fmaxf(s, 0.0f);
#pragma unroll
            for (int k = 0; k < Kv; ++k) wk[k] += s * w2s[k * Hv + j];
        }
#pragma unroll
        for (int k = 0; k < Kv; ++k) g_w[e * Kv + k] = wk[k];
    } else {
        int e = (bid - NB_LINC - NB_K0) * 8 + wid;
        int cnt = scan_row<Nv, CAPE, 4>(rinc + (size_t)e * Nv, nbuf[wid], lane);
        __syncwarp();
        int myn0 = (lane < cnt) ? nbuf[wid][lane] : 0;
        int myn1 = (32 + lane < cnt) ? nbuf[wid][32 + lane] : 0;

        const int boff = (lane >> 2) * (Nv * Cv / 4) + (lane & 3);

        float4 acc[8];
#pragma unroll
        for (int q = 0; q < 8; ++q) acc[q] = make_float4(0.f, 0.f, 0.f, 0.f);

        const float4* x4 = (const float4*)x;
        for (int i = 0; i < cnt; ++i) {
            int nn = (i < 32) ? __shfl_sync(0xffffffffu, myn0, i)
                              : __shfl_sync(0xffffffffu, myn1, i - 32);
            const float4* xn = x4 + (size_t)nn * (Cv / 4) + boff;
#pragma unroll
            for (int q = 0; q < 8; ++q) {
                float4 v = xn[(size_t)q * 8 * (Nv * Cv / 4)];
                acc[q].x += v.x; acc[q].y += v.y; acc[q].z += v.z; acc[q].w += v.w;
            }
        }

        float4* zw = (float4*)(g_z + (size_t)e * (Bv * Cv));
#pragma unroll
        for (int q = 0; q < 8; ++q) zw[q * 32 + lane] = acc[q];
    }
}

// ---------------- K4: persistent fused per-node y + GEMM + relu --------------
// R13 configuration (proven best): grid 444 (3 CTAs/SM), smem 65536:
//   gcw_s @0 (32KB, loaded ONCE) | y_s @32768 (32KB), overlaid per node by
//   {wdup 12288B, el_s 800B} during stage 1. Stage-2 j-loop unroll 4.
#define SMEM4 65536
__global__ void __launch_bounds__(256, 3) k4_main(const float* __restrict__ gcw,
                                                  const float* __restrict__ gcb,
                                                  float* __restrict__ out) {
    extern __shared__ char smem[];
    float* gcw_s = (float*)smem;                   // 32KB, persistent
    u64*   y_s   = (u64*)(smem + 32768);           // 32KB
    u64*   wdup  = (u64*)(smem + 32768);           // overlay: k-duplicated w
    int*   el_s  = (int*)(smem + 45056);           // overlay: padded edge list

    int t = threadIdx.x;

    for (int i = t; i < (Gv * CKv) / 4; i += 256)
        ((float4*)gcw_s)[i] = ((const float4*)gcw)[i];
    const int bq = t & 31, gq = t >> 5;            // stage-2 mapping
    const float4 cb0 = ((const float4*)gcb)[gq * 2];
    const float4 cb1 = ((const float4*)gcb)[gq * 2 + 1];
    const int b = t >> 2, cq = t & 3;              // stage-1 mapping
    const size_t zoff = (size_t)b * Cv + cq * 4;
    const int bx = b ^ (cq << 2);                  // swizzled y column (write side)

    for (int n = blockIdx.x; n < Nv; n += GRID4) {
        __syncthreads();                           // y_s consumed; safe to overlay

        int cnt = g_ncnt[n];
        if (t < CAPNP) el_s[t] = (t < cnt) ? g_nedges[(size_t)n * CAPN + t] : 0;
        if (t < CAPN) {
            if (t < cnt) {
                int e = el_s[t];
                float4 wa = *(const float4*)(g_w + (size_t)e * 8);
                float4 wb = *(const float4*)(g_w + (size_t)e * 8 + 4);
                wdup[t * 8 + 0] = pack2(wa.x, wa.x); wdup[t * 8 + 1] = pack2(wa.y, wa.y);
                wdup[t * 8 + 2] = pack2(wa.z, wa.z); wdup[t * 8 + 3] = pack2(wa.w, wa.w);
                wdup[t * 8 + 4] = pack2(wb.x, wb.x); wdup[t * 8 + 5] = pack2(wb.y, wb.y);
                wdup[t * 8 + 6] = pack2(wb.z, wb.z); wdup[t * 8 + 7] = pack2(wb.w, wb.w);
            } else {
#pragma unroll
                for (int k = 0; k < 8; ++k) wdup[t * 8 + k] = 0ull;
            }
        }
        __syncthreads();

        // ---- stage 1: acc2[cp][k] += zpair(cp) * wdup(k); depth-4 prefetch ----
        u64 acc2[2][8];
#pragma unroll
        for (int cp = 0; cp < 2; ++cp)
#pragma unroll
            for (int k = 0; k < 8; ++k) acc2[cp][k] = 0ull;

        const ulonglong2* w_s2 = (const ulonglong2*)wdup;
        int cnt4 = (cnt + 3) & ~3;                 // padded iters are exact zeros

        float4 pz[4];
#pragma unroll
        for (int u = 0; u < 4; ++u)
            pz[u] = *(const float4*)(g_z + (size_t)el_s[u] * (Bv * Cv) + zoff);

        for (int i = 0; i < cnt4; i += 4) {
#pragma unroll
            for (int u = 0; u < 4; ++u) {
                float4 zv = pz[u];
                pz[u] = *(const float4*)(g_z + (size_t)el_s[i + 4 + u] * (Bv * Cv) + zoff);
                u64 zp0 = pack2(zv.x, zv.y);
                u64 zp1 = pack2(zv.z, zv.w);
                ulonglong2 wd0 = w_s2[(i + u) * 4 + 0];
                ulonglong2 wd1 = w_s2[(i + u) * 4 + 1];
                ulonglong2 wd2 = w_s2[(i + u) * 4 + 2];
                ulonglong2 wd3 = w_s2[(i + u) * 4 + 3];
                ffma2(acc2[0][0], zp0, wd0.x); ffma2(acc2[0][1], zp0, wd0.y);
                ffma2(acc2[0][2], zp0, wd1.x); ffma2(acc2[0][3], zp0, wd1.y);
                ffma2(acc2[0][4], zp0, wd2.x); ffma2(acc2[0][5], zp0, wd2.y);
                ffma2(acc2[0][6], zp0, wd3.x); ffma2(acc2[0][7], zp0, wd3.y);
                ffma2(acc2[1][0], zp1, wd0.x); ffma2(acc2[1][1], zp1, wd0.y);
                ffma2(acc2[1][2], zp1, wd1.x); ffma2(acc2[1][3], zp1, wd1.y);
                ffma2(acc2[1][4], zp1, wd2.x); ffma2(acc2[1][5], zp1, wd2.y);
                ffma2(acc2[1][6], zp1, wd3.x); ffma2(acc2[1][7], zp1, wd3.y);
            }
        }

        // repack c-pairs -> k-pairs (bit-exact)
        float alo[2][8], ahi[2][8];
#pragma unroll
        for (int cp = 0; cp < 2; ++cp)
#pragma unroll
            for (int k = 0; k < 8; ++k) unpack2(alo[cp][k], ahi[cp][k], acc2[cp][k]);

        __syncthreads();                           // wdup/el_s dead

        // write y: slot(j,b) = j*64 + bx  (bx = b ^ 4*cq; j>>4 == cq here)
#pragma unroll
        for (int ci = 0; ci < 4; ++ci) {
            int cp = ci >> 1, eo = ci & 1;
#pragma unroll
            for (int kq = 0; kq < 4; ++kq) {
                float v0 = eo ? ahi[cp][2 * kq]     : alo[cp][2 * kq];
                float v1 = eo ? ahi[cp][2 * kq + 1] : alo[cp][2 * kq + 1];
                int j = (cq * 4 + ci) * 4 + kq;
                y_s[j * 64 + bx] = pack2(v0, v1);
            }
        }
        __syncthreads();

        // ---- stage 2: out[b][g] = relu(sum_j y[j][b]*gcw[g][j] + gcb[g]) ----
        u64 a2[2][8];
#pragma unroll
        for (int ib = 0; ib < 2; ++ib)
#pragma unroll
            for (int ig = 0; ig < 8; ++ig) a2[ib][ig] = 0ull;

        const u64* gc = (const u64*)gcw_s;         // gc[g*64 + j]
#pragma unroll 4
        for (int j2 = 0; j2 < 64; j2 += 2) {
            int c4 = (j2 >> 4) << 2;
            u64 ya0 = y_s[j2 * 64 + (bq ^ c4)];
            u64 ya1 = y_s[j2 * 64 + ((bq + 32) ^ c4)];
            u64 yb0 = y_s[(j2 + 1) * 64 + (bq ^ c4)];
            u64 yb1 = y_s[(j2 + 1) * 64 + ((bq + 32) ^ c4)];
#pragma unroll
            for (int h = 0; h < 2; ++h) {
                ulonglong2 gv[4];
#pragma unroll
                for (int m = 0; m < 4; ++m)
                    gv[m] = *(const ulonglong2*)(gc + (gq * 8 + h * 4 + m) * 64 + j2);
#pragma unroll
                for (int m = 0; m < 4; ++m) {      // j = j2 first (order preserved)
                    ffma2(a2[0][h * 4 + m], ya0, gv[m].x);
                    ffma2(a2[1][h * 4 + m], ya1, gv[m].x);
                }
#pragma unroll
                for (int m = 0; m < 4; ++m) {      // then j = j2+1
                    ffma2(a2[0][h * 4 + m], yb0, gv[m].y);
                    ffma2(a2[1][h * 4 + m], yb1, gv[m].y);
                }
            }
        }

#pragma unroll
        for (int ib = 0; ib < 2; ++ib) {
            int bb = bq + 32 * ib;
            float4 o0, o1;
            o0.x = fmaxf(hsum2(a2[ib][0]) + cb0.x, 0.0f);
            o0.y = fmaxf(hsum2(a2[ib][1]) + cb0.y, 0.0f);
            o0.z = fmaxf(hsum2(a2[ib][2]) + cb0.z, 0.0f);
            o0.w = fmaxf(hsum2(a2[ib][3]) + cb0.w, 0.0f);
            o1.x = fmaxf(hsum2(a2[ib][4]) + cb1.x, 0.0f);
            o1.y = fmaxf(hsum2(a2[ib][5]) + cb1.y, 0.0f);
            o1.z = fmaxf(hsum2(a2[ib][6]) + cb1.z, 0.0f);
            o1.w = fmaxf(hsum2(a2[ib][7]) + cb1.w, 0.0f);
            float* op = out + (size_t)bb * NGv + n * Gv + gq * 8;
            *(float4*)op = o0;
            *(float4*)(op + 4) = o1;
        }
    }
}

// ---------------- launcher ----------------
extern "C" void kernel_launch(void* const* d_in, const int* in_sizes, int n_in,
                              void* d_out, int out_size) {
    const float* x    = (const float*)d_in[0];
    const float* linc = (const float*)d_in[1];
    const float* rinc = (const float*)d_in[2];
    const float* ef   = (const float*)d_in[3];
    const float* w1   = (const float*)d_in[4];
    const float* b1   = (const float*)d_in[5];
    const float* w2   = (const float*)d_in[6];
    const float* b2   = (const float*)d_in[7];
    const float* gcw  = (const float*)d_in[8];
    const float* gcb  = (const float*)d_in[9];
    float* out = (float*)d_out;

    (void)in_sizes; (void)n_in; (void)out_size;

    cudaFuncSetAttribute(k4_main, cudaFuncAttributeMaxDynamicSharedMemorySize, SMEM4);

    k123<<<NB_LINC + NB_K0 + NB_EDGE, 256>>>(rinc, linc, x, ef, w1, b1, w2, b2);
    k4_main<<<GRID4, 256, SMEM4>>>(gcw, gcb, out);
}

// round 16
// speedup vs baseline: 1.2606x; 1.0597x over previous
#include <cuda_runtime.h>
#include <cstddef>
#include <cstdint>

// Problem constants
#define Bv 64
#define Nv 2048
#define Ev 16384
#define Fv 32
#define Hv 64
#define Kv 8
#define Cv 16
#define Gv 64
#define CKv 128          // C*K
#define NGv 131072       // N*G
#define CAPE 64          // max nodes per edge (mean 8)
#define CAPN 192         // max edges per node (mean 64)
#define CAPNP (CAPN + 8) // padded edge list (prefetch overrun guard)
#define GRID4 444        // persistent K4 grid = 3 CTAs x 148 SMs

// fused front kernel block ranges
#define NB_LINC 256      // linc scan: 256 blocks x 8 warps = 2048 node rows
#define NB_K0   64       // edge MLP: 64 blocks x 256 threads = 16384 edges
#define NB_EDGE 2048     // rinc scan + gather: 2048 blocks x 8 warps = 16384 edges

typedef unsigned long long u64;

__device__ __forceinline__ u64 pack2(float lo, float hi) {
    u64 r; asm("mov.b64 %0,{%1,%2};" : "=l"(r) : "f"(lo), "f"(hi)); return r;
}
__device__ __forceinline__ void ffma2(u64& d, u64 a, u64 b) {
    asm("fma.rn.f32x2 %0,%1,%2,%0;" : "+l"(d) : "l"(a), "l"(b));
}
__device__ __forceinline__ void unpack2(float& lo, float& hi, u64 v) {
    asm("mov.b64 {%0,%1},%2;" : "=f"(lo), "=f"(hi) : "l"(v));
}
__device__ __forceinline__ float hsum2(u64 v) {
    float lo, hi; unpack2(lo, hi, v);
    return lo + hi;
}

// ---------------- scratch (device globals; no allocation) ----------------
__device__ float g_w[Ev * Kv];                 // per-edge kernel weights [E,K]
__device__ int   g_ncnt[Nv];
__device__ int   g_nedges[Nv * CAPN];          // linc CSR: edges per node
__device__ float g_z[(size_t)Ev * Bv * Cv];    // z in (E,B,C) layout, 67MB

// ---------------- ordered sparse row scan (deterministic compaction) ---------
template <int COLS, int CAP, int UNROLL>
__device__ __forceinline__ int scan_row(const float* __restrict__ row,
                                        int* __restrict__ outp, int lane) {
    int cnt = 0;
    const float4* r4 = (const float4*)row;
    const unsigned lt = (1u << lane) - 1u;
    for (int g = 0; g < COLS / 128; g += UNROLL) {
        float4 v[UNROLL];
#pragma unroll
        for (int u = 0; u < UNROLL; ++u) v[u] = r4[(size_t)(g + u) * 32 + lane];
#pragma unroll
        for (int u = 0; u < UNROLL; ++u) {
            float a0 = v[u].x, a1 = v[u].y, a2 = v[u].z, a3 = v[u].w;
            unsigned m0 = __ballot_sync(0xffffffffu, a0 != 0.0f);
            unsigned m1 = __ballot_sync(0xffffffffu, a1 != 0.0f);
            unsigned m2 = __ballot_sync(0xffffffffu, a2 != 0.0f);
            unsigned m3 = __ballot_sync(0xffffffffu, a3 != 0.0f);
            int prefix = __popc(m0 & lt) + __popc(m1 & lt) + __popc(m2 & lt) + __popc(m3 & lt);
            int base = (g + u) * 128 + lane * 4;
            int own = 0;
            if (a0 != 0.0f) { int p = cnt + prefix + own; if (p < CAP) outp[p] = base + 0; own++; }
            if (a1 != 0.0f) { int p = cnt + prefix + own; if (p < CAP) outp[p] = base + 1; own++; }
            if (a2 != 0.0f) { int p = cnt + prefix + own; if (p < CAP) outp[p] = base + 2; own++; }
            if (a3 != 0.0f) { int p = cnt + prefix + own; if (p < CAP) outp[p] = base + 3; own++; }
            cnt += __popc(m0) + __popc(m1) + __popc(m2) + __popc(m3);
        }
    }
    return (cnt < CAP) ? cnt : CAP;
}

// ---------------- K123: fused linc scan | edge MLP | rinc scan + gather ------
__global__ void k123(const float* __restrict__ rinc,
                     const float* __restrict__ linc,
                     const float* __restrict__ x,
                     const float* __restrict__ ef,
                     const float* __restrict__ w1, const float* __restrict__ b1,
                     const float* __restrict__ w2, const float* __restrict__ b2) {
    __shared__ int   nbuf[8][CAPE];    // per-warp node lists (gather branch)
    __shared__ float w1s[Hv * Fv];     // k0 branch
    __shared__ float w2s[Kv * Hv];
    __shared__ float b1s[Hv];
    __shared__ float b2s[Kv];

    int bid = blockIdx.x;
    int t = threadIdx.x;
    int wid = t >> 5, lane = t & 31;

    if (bid < NB_LINC) {
        int n = bid * 8 + wid;
        int c = scan_row<Ev, CAPN, 8>(linc + (size_t)n * Ev,
                                      g_nedges + (size_t)n * CAPN, lane);
        if (lane == 0) g_ncnt[n] = c;
    } else if (bid < NB_LINC + NB_K0) {
        int e = (bid - NB_LINC) * 256 + t;
        for (int i = t; i < Hv * Fv; i += 256) w1s[i] = w1[i];
        for (int i = t; i < Kv * Hv; i += 256) w2s[i] = w2[i];
        if (t < Hv) b1s[t] = b1[t];
        if (t < Kv) b2s[t] = b2[t];
        __syncthreads();

        float efr[Fv];
#pragma unroll
        for (int q = 0; q < Fv / 4; ++q)
            ((float4*)efr)[q] = ((const float4*)(ef + (size_t)e * Fv))[q];
        float wk[Kv];
#pragma unroll
        for (int k = 0; k < Kv; ++k) wk[k] = b2s[k];
        for (int j = 0; j < Hv; ++j) {
            float s = b1s[j];
#pragma unroll
            for (int f = 0; f < Fv; ++f) s += efr[f] * w1s[j * Fv + f];
            s = fmaxf(s, 0.0f);
#pragma unroll
            for (int k = 0; k < Kv; ++k) wk[k] += s * w2s[k * Hv + j];
        }
#pragma unroll
        for (int k = 0; k < Kv; ++k) g_w[e * Kv + k] = wk[k];
    } else {
        int e = (bid - NB_LINC - NB_K0) * 8 + wid;
        int cnt = scan_row<Nv, CAPE, 4>(rinc + (size_t)e * Nv, nbuf[wid], lane);
        __syncwarp();
        int myn0 = (lane < cnt) ? nbuf[wid][lane] : 0;
        int myn1 = (32 + lane < cnt) ? nbuf[wid][32 + lane] : 0;

        const int boff = (lane >> 2) * (Nv * Cv / 4) + (lane & 3);

        float4 acc[8];
#pragma unroll
        for (int q = 0; q < 8; ++q) acc[q] = make_float4(0.f, 0.f, 0.f, 0.f);

        const float4* x4 = (const float4*)x;
        for (int i = 0; i < cnt; ++i) {
            int nn = (i < 32) ? __shfl_sync(0xffffffffu, myn0, i)
                              : __shfl_sync(0xffffffffu, myn1, i - 32);
            const float4* xn = x4 + (size_t)nn * (Cv / 4) + boff;
#pragma unroll
            for (int q = 0; q < 8; ++q) {
                float4 v = xn[(size_t)q * 8 * (Nv * Cv / 4)];
                acc[q].x += v.x; acc[q].y += v.y; acc[q].z += v.z; acc[q].w += v.w;
            }
        }

        float4* zw = (float4*)(g_z + (size_t)e * (Bv * Cv));
#pragma unroll
        for (int q = 0; q < 8; ++q) zw[q * 32 + lane] = acc[q];
    }
}

// ---------------- K4: persistent fused per-node y + GEMM + relu --------------
// R15 configuration, stage-1 load scheme swapped:
//   w stored as plain k-pairs (u64) -> 2 uniform LDS.128 per edge (was 4)
//   z c-duplicated via 4 pack2 MOVs (alu pipe has headroom; L1 is binding)
//   k-pair accumulators write y directly (repack eliminated)
// smem 65536: gcw_s @0 (32KB) | y_s @32768 (32KB), overlaid per node by
//   {wk_s 6144B, el_s 800B} during stage 1. Stage-2 unroll 4 (R15).
#define SMEM4 65536
__global__ void __launch_bounds__(256, 3) k4_main(const float* __restrict__ gcw,
                                                  const float* __restrict__ gcb,
                                                  float* __restrict__ out) {
    extern __shared__ char smem[];
    float* gcw_s = (float*)smem;                   // 32KB, persistent
    u64*   y_s   = (u64*)(smem + 32768);           // 32KB
    u64*   wk_s  = (u64*)(smem + 32768);           // overlay: w k-pairs (CAPN*4 u64)
    int*   el_s  = (int*)(smem + 32768 + CAPN * 4 * 8);  // overlay: edge list

    int t = threadIdx.x;

    for (int i = t; i < (Gv * CKv) / 4; i += 256)
        ((float4*)gcw_s)[i] = ((const float4*)gcw)[i];
    const int bq = t & 31, gq = t >> 5;            // stage-2 mapping
    const float4 cb0 = ((const float4*)gcb)[gq * 2];
    const float4 cb1 = ((const float4*)gcb)[gq * 2 + 1];
    const int b = t >> 2, cq = t & 3;              // stage-1 mapping
    const size_t zoff = (size_t)b * Cv + cq * 4;
    const int bx = b ^ (cq << 2);                  // swizzled y column (write side)

    for (int n = blockIdx.x; n < Nv; n += GRID4) {
        __syncthreads();                           // y_s consumed; safe to overlay

        int cnt = g_ncnt[n];
        if (t < CAPNP) el_s[t] = (t < cnt) ? g_nedges[(size_t)n * CAPN + t] : 0;
        if (t < CAPN) {
            if (t < cnt) {
                int e = el_s[t];
                // straight copy: g_w row IS the k-pair layout (w2q, w2q+1)
                ulonglong2 wa = *(const ulonglong2*)(g_w + (size_t)e * 8);
                ulonglong2 wb = *(const ulonglong2*)(g_w + (size_t)e * 8 + 4);
                *(ulonglong2*)(wk_s + t * 4)     = wa;
                *(ulonglong2*)(wk_s + t * 4 + 2) = wb;
            } else {
                *(ulonglong2*)(wk_s + t * 4)     = make_ulonglong2(0ull, 0ull);
                *(ulonglong2*)(wk_s + t * 4 + 2) = make_ulonglong2(0ull, 0ull);
            }
        }
        __syncthreads();

        // ---- stage 1: acc[c][kq] += zdup(c) * wpair(kq); depth-4 prefetch ----
        u64 acc[4][4];
#pragma unroll
        for (int ci = 0; ci < 4; ++ci)
#pragma unroll
            for (int kq = 0; kq < 4; ++kq) acc[ci][kq] = 0ull;

        const ulonglong2* wk2 = (const ulonglong2*)wk_s;
        int cnt4 = (cnt + 3) & ~3;                 // padded iters are exact zeros

        float4 pz[4];
#pragma unroll
        for (int u = 0; u < 4; ++u)
            pz[u] = *(const float4*)(g_z + (size_t)el_s[u] * (Bv * Cv) + zoff);

        for (int i = 0; i < cnt4; i += 4) {
#pragma unroll
            for (int u = 0; u < 4; ++u) {
                float4 zv = pz[u];
                pz[u] = *(const float4*)(g_z + (size_t)el_s[i + 4 + u] * (Bv * Cv) + zoff);
                u64 z0 = pack2(zv.x, zv.x), z1 = pack2(zv.y, zv.y);
                u64 z2 = pack2(zv.z, zv.z), z3 = pack2(zv.w, zv.w);
                ulonglong2 wp01 = wk2[(i + u) * 2 + 0];   // k-pairs (0,1),(2,3)
                ulonglong2 wp23 = wk2[(i + u) * 2 + 1];   // k-pairs (4,5),(6,7)
                ffma2(acc[0][0], z0, wp01.x); ffma2(acc[0][1], z0, wp01.y);
                ffma2(acc[0][2], z0, wp23.x); ffma2(acc[0][3], z0, wp23.y);
                ffma2(acc[1][0], z1, wp01.x); ffma2(acc[1][1], z1, wp01.y);
                ffma2(acc[1][2], z1, wp23.x); ffma2(acc[1][3], z1, wp23.y);
                ffma2(acc[2][0], z2, wp01.x); ffma2(acc[2][1], z2, wp01.y);
                ffma2(acc[2][2], z2, wp23.x); ffma2(acc[2][3], z2, wp23.y);
                ffma2(acc[3][0], z3, wp01.x); ffma2(acc[3][1], z3, wp01.y);
                ffma2(acc[3][2], z3, wp23.x); ffma2(acc[3][3], z3, wp23.y);
            }
        }

        __syncthreads();                           // wk_s/el_s dead

        // write y: acc[ci][kq] IS the k-pair j = (cq*4+ci)*4+kq (no repack)
#pragma unroll
        for (int ci = 0; ci < 4; ++ci)
#pragma unroll
            for (int kq = 0; kq < 4; ++kq) {
                int j = (cq * 4 + ci) * 4 + kq;
                y_s[j * 64 + bx] = acc[ci][kq];
            }
        __syncthreads();

        // ---- stage 2: out[b][g] = relu(sum_j y[j][b]*gcw[g][j] + gcb[g]) ----
        u64 a2[2][8];
#pragma unroll
        for (int ib = 0; ib < 2; ++ib)
#pragma unroll
            for (int ig = 0; ig < 8; ++ig) a2[ib][ig] = 0ull;

        const u64* gc = (const u64*)gcw_s;         // gc[g*64 + j]
#pragma unroll 4
        for (int j2 = 0; j2 < 64; j2 += 2) {
            int c4 = (j2 >> 4) << 2;
            u64 ya0 = y_s[j2 * 64 + (bq ^ c4)];
            u64 ya1 = y_s[j2 * 64 + ((bq + 32) ^ c4)];
            u64 yb0 = y_s[(j2 + 1) * 64 + (bq ^ c4)];
            u64 yb1 = y_s[(j2 + 1) * 64 + ((bq + 32) ^ c4)];
#pragma unroll
            for (int h = 0; h < 2; ++h) {
                ulonglong2 gv[4];
#pragma unroll
                for (int m = 0; m < 4; ++m)
                    gv[m] = *(const ulonglong2*)(gc + (gq * 8 + h * 4 + m) * 64 + j2);
#pragma unroll
                for (int m = 0; m < 4; ++m) {      // j = j2 first (order preserved)
                    ffma2(a2[0][h * 4 + m], ya0, gv[m].x);
                    ffma2(a2[1][h * 4 + m], ya1, gv[m].x);
                }
#pragma unroll
                for (int m = 0; m < 4; ++m) {      // then j = j2+1
                    ffma2(a2[0][h * 4 + m], yb0, gv[m].y);
                    ffma2(a2[1][h * 4 + m], yb1, gv[m].y);
                }
            }
        }

#pragma unroll
        for (int ib = 0; ib < 2; ++ib) {
            int bb = bq + 32 * ib;
            float4 o0, o1;
            o0.x = fmaxf(hsum2(a2[ib][0]) + cb0.x, 0.0f);
            o0.y = fmaxf(hsum2(a2[ib][1]) + cb0.y, 0.0f);
            o0.z = fmaxf(hsum2(a2[ib][2]) + cb0.z, 0.0f);
            o0.w = fmaxf(hsum2(a2[ib][3]) + cb0.w, 0.0f);
            o1.x = fmaxf(hsum2(a2[ib][4]) + cb1.x, 0.0f);
            o1.y = fmaxf(hsum2(a2[ib][5]) + cb1.y, 0.0f);
            o1.z = fmaxf(hsum2(a2[ib][6]) + cb1.z, 0.0f);
            o1.w = fmaxf(hsum2(a2[ib][7]) + cb1.w, 0.0f);
            float* op = out + (size_t)bb * NGv + n * Gv + gq * 8;
            *(float4*)op = o0;
            *(float4*)(op + 4) = o1;
        }
    }
}

// ---------------- launcher ----------------
extern "C" void kernel_launch(void* const* d_in, const int* in_sizes, int n_in,
                              void* d_out, int out_size) {
    const float* x    = (const float*)d_in[0];
    const float* linc = (const float*)d_in[1];
    const float* rinc = (const float*)d_in[2];
    const float* ef   = (const float*)d_in[3];
    const float* w1   = (const float*)d_in[4];
    const float* b1   = (const float*)d_in[5];
    const float* w2   = (const float*)d_in[6];
    const float* b2   = (const float*)d_in[7];
    const float* gcw  = (const float*)d_in[8];
    const float* gcb  = (const float*)d_in[9];
    float* out = (float*)d_out;

    (void)in_sizes; (void)n_in; (void)out_size;

    cudaFuncSetAttribute(k4_main, cudaFuncAttributeMaxDynamicSharedMemorySize, SMEM4);

    k123<<<NB_LINC + NB_K0 + NB_EDGE, 256>>>(rinc, linc, x, ef, w1, b1, w2, b2);
    k4_main<<<GRID4, 256, SMEM4>>>(gcw, gcb, out);
}